// round 7
// baseline (speedup 1.0000x reference)
#include <cuda_runtime.h>
#include <cstdint>

#define N_USERS 40000
#define N_ITEMS 60000
#define N_NODES 100000
#define N_EDGES 1280000
#define EMB 64
#define NEG_SLOPE 0.2f

#define SCAN_BLK 1024
#define NSCAN_BLOCKS ((N_NODES + SCAN_BLK - 1) / SCAN_BLK)   // 98
#define TN 128             // nodes per dense block
#define LDUV 132           // padded transposed-tile stride (floats)

// Scratch
__device__ float g_e[N_NODES * EMB];
__device__ float g_x[N_NODES * EMB];
__device__ int   g_deg[N_NODES];
__device__ int   g_off[N_NODES];
__device__ int   g_head[N_NODES];
__device__ int   g_bsum[NSCAN_BLOCKS];   // per-scan-block totals
__device__ int2  g_csr_cv[N_EDGES];

// ---------------------------------------------------------------------------
// f32x2 helpers
// ---------------------------------------------------------------------------
__device__ __forceinline__ unsigned long long dup2(float x) {
    unsigned long long r;
    asm("mov.b64 %0, {%1, %1};" : "=l"(r) : "f"(x));
    return r;
}
__device__ __forceinline__ void fma2(unsigned long long& d,
                                     unsigned long long a, unsigned long long b) {
    asm("fma.rn.f32x2 %0, %1, %2, %0;" : "+l"(d) : "l"(a), "l"(b));
}
__device__ __forceinline__ float2 unpk(unsigned long long v) {
    float2 r;
    asm("mov.b64 {%0, %1}, %2;" : "=f"(r.x), "=f"(r.y) : "l"(v));
    return r;
}

// ---------------------------------------------------------------------------
// init: e = concat(user_emb, item_emb); acc (d_out) = e ; deg = 0
// ---------------------------------------------------------------------------
__global__ void k_init(const float* __restrict__ ue, const float* __restrict__ ie,
                       float* __restrict__ out) {
    int i = blockIdx.x * blockDim.x + threadIdx.x;
    const int total4 = N_NODES * EMB / 4;
    if (i < N_NODES) g_deg[i] = 0;
    if (i >= total4) return;
    const int user4 = N_USERS * EMB / 4;
    float4 v;
    if (i < user4) v = ((const float4*)ue)[i];
    else           v = ((const float4*)ie)[i - user4];
    ((float4*)g_e)[i] = v;
    ((float4*)out)[i] = v;
}

// ---------------------------------------------------------------------------
// CSR build: hist -> scanA -> scanC (self-carry) -> scatter
// ---------------------------------------------------------------------------
__global__ void k_hist(const int* __restrict__ erow) {
    int i = blockIdx.x * blockDim.x + threadIdx.x;
    if (i < N_EDGES) atomicAdd(&g_deg[erow[i]], 1);
}

__global__ void __launch_bounds__(SCAN_BLK) k_scanA() {
    __shared__ int s[SCAN_BLK];
    int i = blockIdx.x * SCAN_BLK + threadIdx.x;
    int v = (i < N_NODES) ? g_deg[i] : 0;
    s[threadIdx.x] = v;
    __syncthreads();
    int inc = v;
    #pragma unroll
    for (int d = 1; d < SCAN_BLK; d <<= 1) {
        int t = (threadIdx.x >= d) ? s[threadIdx.x - d] : 0;
        __syncthreads();
        inc += t;
        s[threadIdx.x] = inc;
        __syncthreads();
    }
    if (i < N_NODES) g_off[i] = inc - v;          // exclusive within block
    if (threadIdx.x == SCAN_BLK - 1) g_bsum[blockIdx.x] = inc;   // block total
}

// scanC: each block computes its own carry (sum of scan-block totals before it)
__global__ void __launch_bounds__(256) k_scanC() {
    __shared__ int s_carry;
    int sb = blockIdx.x >> 2;          // 256*4 = 1024 = SCAN_BLK
    if (threadIdx.x < 32) {
        int sum = 0;
        for (int i = threadIdx.x; i < sb; i += 32) sum += g_bsum[i];
        #pragma unroll
        for (int d = 16; d; d >>= 1) sum += __shfl_xor_sync(0xffffffffu, sum, d);
        if (threadIdx.x == 0) s_carry = sum;
    }
    __syncthreads();
    int i = blockIdx.x * 256 + threadIdx.x;
    if (i >= N_NODES) return;
    int o = g_off[i] + s_carry;
    g_off[i] = o;
    g_head[i] = o;
}

__global__ void k_scatter(const int* __restrict__ erow, const int* __restrict__ ecol,
                          const float* __restrict__ eval) {
    int i = blockIdx.x * blockDim.x + threadIdx.x;
    if (i >= N_EDGES) return;
    int r = erow[i];
    int pos = atomicAdd(&g_head[r], 1);
    g_csr_cv[pos] = make_int2(ecol[i], __float_as_int(eval[i]));
}

// ---------------------------------------------------------------------------
// CSR SpMM (gather, no atomics), edge loop unrolled x4
// ---------------------------------------------------------------------------
__global__ void __launch_bounds__(256) k_spmm_csr() {
    int t = blockIdx.x * blockDim.x + threadIdx.x;
    int node = t >> 4;
    int c = t & 15;
    if (node >= N_NODES) return;
    int start = g_off[node];
    int deg = g_deg[node];

    float4 a0 = make_float4(0.f, 0.f, 0.f, 0.f);
    float4 a1 = make_float4(0.f, 0.f, 0.f, 0.f);
    int j = 0;
    for (; j + 3 < deg; j += 4) {
        int2 cv0 = g_csr_cv[start + j];
        int2 cv1 = g_csr_cv[start + j + 1];
        int2 cv2 = g_csr_cv[start + j + 2];
        int2 cv3 = g_csr_cv[start + j + 3];
        float4 f0 = __ldg(((const float4*)g_e) + cv0.x * 16 + c);
        float4 f1 = __ldg(((const float4*)g_e) + cv1.x * 16 + c);
        float4 f2 = __ldg(((const float4*)g_e) + cv2.x * 16 + c);
        float4 f3 = __ldg(((const float4*)g_e) + cv3.x * 16 + c);
        float v0 = __int_as_float(cv0.y);
        float v1 = __int_as_float(cv1.y);
        float v2 = __int_as_float(cv2.y);
        float v3 = __int_as_float(cv3.y);
        a0.x += v0 * f0.x; a0.y += v0 * f0.y; a0.z += v0 * f0.z; a0.w += v0 * f0.w;
        a1.x += v1 * f1.x; a1.y += v1 * f1.y; a1.z += v1 * f1.z; a1.w += v1 * f1.w;
        a0.x += v2 * f2.x; a0.y += v2 * f2.y; a0.z += v2 * f2.z; a0.w += v2 * f2.w;
        a1.x += v3 * f3.x; a1.y += v3 * f3.y; a1.z += v3 * f3.z; a1.w += v3 * f3.w;
    }
    for (; j < deg; j++) {
        int2 cv0 = g_csr_cv[start + j];
        float v0 = __int_as_float(cv0.y);
        float4 f0 = __ldg(((const float4*)g_e) + cv0.x * 16 + c);
        a0.x += v0 * f0.x; a0.y += v0 * f0.y; a0.z += v0 * f0.z; a0.w += v0 * f0.w;
    }
    a0.x += a1.x; a0.y += a1.y; a0.z += a1.z; a0.w += a1.w;
    ((float4*)g_x)[node * 16 + c] = a0;
}

// ---------------------------------------------------------------------------
// Dense layer, f32x2 node-pair version with smem W:
// h = (e+x)@W1 + (x*e)@W2 + b ; lrelu ; l2norm -> e ; out = (out+e)*scale
// Block: 128 nodes x 64 cols, 256 threads; thread = 8 nodes (4 pairs) x 4 cols.
// ---------------------------------------------------------------------------
extern __shared__ float s_dyn[];   // sW[64*64] + sUV[64*LDUV]

__global__ void __launch_bounds__(256) k_dense(
    const float* __restrict__ W1, const float* __restrict__ b1,
    const float* __restrict__ W2, const float* __restrict__ b2,
    float* __restrict__ out, float scale) {

    float* sW  = s_dyn;              // 64*64 floats
    float* sUV = s_dyn + 64 * 64;    // 64*LDUV floats

    const int tid = threadIdx.x;
    const int tx = tid & 15;         // cols tx*4 .. +3
    const int ty = tid >> 4;         // nodes ty*8 .. +7
    const int base = blockIdx.x * TN;

    unsigned long long acc[4][4];    // [node pair][col]
    #pragma unroll
    for (int p = 0; p < 4; p++)
        #pragma unroll
        for (int j = 0; j < 4; j++) acc[p][j] = 0ull;

    #pragma unroll
    for (int ph = 0; ph < 2; ph++) {
        if (ph) __syncthreads();
        const float* W = ph ? W2 : W1;

        // W tile: 1024 float4 over 256 threads
        #pragma unroll
        for (int it = 0; it < 4; it++) {
            int i = tid + it * 256;
            ((float4*)sW)[i] = ((const float4*)W)[i];
        }
        // transposed U (ph0: e+x) / V (ph1: e*x) tile: [k][node]
        #pragma unroll
        for (int it = 0; it < 8; it++) {
            int i = tid + it * 256;          // 0..2047
            int nd = i >> 4;                 // local node 0..127
            int c4 = i & 15;                 // float4 chunk
            int node = base + nd;
            float4 ev = make_float4(0.f, 0.f, 0.f, 0.f);
            float4 xv = make_float4(0.f, 0.f, 0.f, 0.f);
            if (node < N_NODES) {
                ev = ((const float4*)g_e)[node * 16 + c4];
                xv = ((const float4*)g_x)[node * 16 + c4];
            }
            float4 u;
            if (ph == 0) u = make_float4(ev.x + xv.x, ev.y + xv.y, ev.z + xv.z, ev.w + xv.w);
            else         u = make_float4(ev.x * xv.x, ev.y * xv.y, ev.z * xv.z, ev.w * xv.w);
            int r0 = c4 * 4;
            sUV[(r0 + 0) * LDUV + nd] = u.x;
            sUV[(r0 + 1) * LDUV + nd] = u.y;
            sUV[(r0 + 2) * LDUV + nd] = u.z;
            sUV[(r0 + 3) * LDUV + nd] = u.w;
        }
        __syncthreads();

        #pragma unroll 8
        for (int k = 0; k < 64; k++) {
            float4 w = *(const float4*)&sW[k * 64 + tx * 4];
            unsigned long long w0 = dup2(w.x);
            unsigned long long w1 = dup2(w.y);
            unsigned long long w2 = dup2(w.z);
            unsigned long long w3 = dup2(w.w);
            const ulonglong2* su = (const ulonglong2*)&sUV[k * LDUV + ty * 8];
            ulonglong2 ua = su[0];   // node pairs (0,1),(2,3)
            ulonglong2 ub = su[1];   // node pairs (4,5),(6,7)
            fma2(acc[0][0], ua.x, w0); fma2(acc[0][1], ua.x, w1);
            fma2(acc[0][2], ua.x, w2); fma2(acc[0][3], ua.x, w3);
            fma2(acc[1][0], ua.y, w0); fma2(acc[1][1], ua.y, w1);
            fma2(acc[1][2], ua.y, w2); fma2(acc[1][3], ua.y, w3);
            fma2(acc[2][0], ub.x, w0); fma2(acc[2][1], ub.x, w1);
            fma2(acc[2][2], ub.x, w2); fma2(acc[2][3], ub.x, w3);
            fma2(acc[3][0], ub.y, w0); fma2(acc[3][1], ub.y, w1);
            fma2(acc[3][2], ub.y, w2); fma2(acc[3][3], ub.y, w3);
        }
    }

    // epilogue
    const int j0 = tx * 4;
    float bb0 = b1[j0 + 0] + b2[j0 + 0];
    float bb1 = b1[j0 + 1] + b2[j0 + 1];
    float bb2 = b1[j0 + 2] + b2[j0 + 2];
    float bb3 = b1[j0 + 3] + b2[j0 + 3];

    #pragma unroll
    for (int p = 0; p < 4; p++) {
        float2 a0 = unpk(acc[p][0]);
        float2 a1 = unpk(acc[p][1]);
        float2 a2 = unpk(acc[p][2]);
        float2 a3 = unpk(acc[p][3]);
        #pragma unroll
        for (int s = 0; s < 2; s++) {
            float h0 = (s ? a0.y : a0.x) + bb0;
            float h1 = (s ? a1.y : a1.x) + bb1;
            float h2 = (s ? a2.y : a2.x) + bb2;
            float h3 = (s ? a3.y : a3.x) + bb3;
            h0 = (h0 >= 0.f) ? h0 : NEG_SLOPE * h0;
            h1 = (h1 >= 0.f) ? h1 : NEG_SLOPE * h1;
            h2 = (h2 >= 0.f) ? h2 : NEG_SLOPE * h2;
            h3 = (h3 >= 0.f) ? h3 : NEG_SLOPE * h3;
            float ss = h0 * h0 + h1 * h1 + h2 * h2 + h3 * h3;
            ss += __shfl_xor_sync(0xffffffffu, ss, 1);
            ss += __shfl_xor_sync(0xffffffffu, ss, 2);
            ss += __shfl_xor_sync(0xffffffffu, ss, 4);
            ss += __shfl_xor_sync(0xffffffffu, ss, 8);
            float inv = rsqrtf(fmaxf(ss, 1e-24f));
            float e0 = h0 * inv, e1 = h1 * inv, e2 = h2 * inv, e3 = h3 * inv;

            int node = base + ty * 8 + p * 2 + s;
            if (node < N_NODES) {
                ((float4*)g_e)[node * 16 + tx] = make_float4(e0, e1, e2, e3);
                float4 o = ((float4*)out)[node * 16 + tx];
                o.x = (o.x + e0) * scale;
                o.y = (o.y + e1) * scale;
                o.z = (o.z + e2) * scale;
                o.w = (o.w + e3) * scale;
                ((float4*)out)[node * 16 + tx] = o;
            }
        }
    }
}

// ---------------------------------------------------------------------------
extern "C" void kernel_launch(void* const* d_in, const int* in_sizes, int n_in,
                              void* d_out, int out_size) {
    const int*   erow = (const int*)d_in[0];
    const int*   ecol = (const int*)d_in[1];
    const float* eval = (const float*)d_in[2];
    const float* ue   = (const float*)d_in[3];
    const float* ie   = (const float*)d_in[4];
    const float* W1   = (const float*)d_in[5];
    const float* b1   = (const float*)d_in[6];
    const float* W2   = (const float*)d_in[7];
    const float* b2   = (const float*)d_in[8];
    float* out = (float*)d_out;

    const int total4 = N_NODES * EMB / 4;
    const int init_blocks = (total4 + 255) / 256;           // 6250
    const int edge_blocks = (N_EDGES + 255) / 256;          // 5000
    const int node_blocks = (N_NODES + 255) / 256;          // 391
    const int spmm_blocks = (N_NODES * 16 + 255) / 256;     // 6250
    const int dense_blocks = (N_NODES + TN - 1) / TN;       // 782
    const int smem_bytes = (64 * 64 + 64 * LDUV) * (int)sizeof(float);  // 50176

    cudaFuncSetAttribute(k_dense, cudaFuncAttributeMaxDynamicSharedMemorySize,
                         smem_bytes);

    k_init<<<init_blocks, 256>>>(ue, ie, out);
    k_hist<<<edge_blocks, 256>>>(erow);
    k_scanA<<<NSCAN_BLOCKS, SCAN_BLK>>>();
    k_scanC<<<node_blocks, 256>>>();
    k_scatter<<<edge_blocks, 256>>>(erow, ecol, eval);

    for (int l = 0; l < 3; l++) {
        k_spmm_csr<<<spmm_blocks, 256>>>();
        float scale = (l == 2) ? 0.25f : 1.0f;
        k_dense<<<dense_blocks, 256, smem_bytes>>>(
            W1 + l * EMB * EMB, b1 + l * EMB,
            W2 + l * EMB * EMB, b2 + l * EMB, out, scale);
    }
}

// round 8
// speedup vs baseline: 1.0684x; 1.0684x over previous
#include <cuda_runtime.h>
#include <cstdint>

#define N_USERS 40000
#define N_ITEMS 60000
#define N_NODES 100000
#define N_EDGES 1280000
#define EMB 64
#define NEG_SLOPE 0.2f

#define SCAN_BLK 1024
#define NSCAN_BLOCKS ((N_NODES + SCAN_BLK - 1) / SCAN_BLK)   // 98

// Scratch: double-buffered embeddings
__device__ float g_ea[N_NODES * EMB];
__device__ float g_eb[N_NODES * EMB];
__device__ int   g_deg[N_NODES];
__device__ int   g_off[N_NODES];
__device__ int   g_head[N_NODES];
__device__ int   g_bsum[NSCAN_BLOCKS];
__device__ int2  g_csr_cv[N_EDGES];

// ---------------------------------------------------------------------------
// init: g_ea = concat(user_emb, item_emb); acc (d_out) = same ; deg = 0
// ---------------------------------------------------------------------------
__global__ void k_init(const float* __restrict__ ue, const float* __restrict__ ie,
                       float* __restrict__ out) {
    int i = blockIdx.x * blockDim.x + threadIdx.x;
    const int total4 = N_NODES * EMB / 4;
    if (i < N_NODES) g_deg[i] = 0;
    if (i >= total4) return;
    const int user4 = N_USERS * EMB / 4;
    float4 v;
    if (i < user4) v = ((const float4*)ue)[i];
    else           v = ((const float4*)ie)[i - user4];
    ((float4*)g_ea)[i] = v;
    ((float4*)out)[i] = v;
}

// ---------------------------------------------------------------------------
// CSR build: hist -> scanA -> scanC (self-carry) -> scatter
// ---------------------------------------------------------------------------
__global__ void k_hist(const int* __restrict__ erow) {
    int i = blockIdx.x * blockDim.x + threadIdx.x;
    if (i < N_EDGES) atomicAdd(&g_deg[erow[i]], 1);
}

__global__ void __launch_bounds__(SCAN_BLK) k_scanA() {
    __shared__ int s[SCAN_BLK];
    int i = blockIdx.x * SCAN_BLK + threadIdx.x;
    int v = (i < N_NODES) ? g_deg[i] : 0;
    s[threadIdx.x] = v;
    __syncthreads();
    int inc = v;
    #pragma unroll
    for (int d = 1; d < SCAN_BLK; d <<= 1) {
        int t = (threadIdx.x >= d) ? s[threadIdx.x - d] : 0;
        __syncthreads();
        inc += t;
        s[threadIdx.x] = inc;
        __syncthreads();
    }
    if (i < N_NODES) g_off[i] = inc - v;
    if (threadIdx.x == SCAN_BLK - 1) g_bsum[blockIdx.x] = inc;
}

__global__ void __launch_bounds__(256) k_scanC() {
    __shared__ int s_carry;
    int sb = blockIdx.x >> 2;          // 256*4 = SCAN_BLK
    if (threadIdx.x < 32) {
        int sum = 0;
        for (int i = threadIdx.x; i < sb; i += 32) sum += g_bsum[i];
        #pragma unroll
        for (int d = 16; d; d >>= 1) sum += __shfl_xor_sync(0xffffffffu, sum, d);
        if (threadIdx.x == 0) s_carry = sum;
    }
    __syncthreads();
    int i = blockIdx.x * 256 + threadIdx.x;
    if (i >= N_NODES) return;
    int o = g_off[i] + s_carry;
    g_off[i] = o;
    g_head[i] = o;
}

__global__ void k_scatter(const int* __restrict__ erow, const int* __restrict__ ecol,
                          const float* __restrict__ eval) {
    int i = blockIdx.x * blockDim.x + threadIdx.x;
    if (i >= N_EDGES) return;
    int r = erow[i];
    int pos = atomicAdd(&g_head[r], 1);
    g_csr_cv[pos] = make_int2(ecol[i], __float_as_int(eval[i]));
}

// ---------------------------------------------------------------------------
// Fused layer: per 64-node block
//   gather x = CSR-spmm rows (registers) ; build sU = e+x, sV = e*x (transposed)
//   h = U@W1 + V@W2 + b ; lrelu ; l2norm -> e_dst ; out = (out+e)*scale
// flag=0: read g_ea write g_eb ; flag=1: read g_eb write g_ea
// Dynamic smem: sW[64*64] + sU[64*67] + sV[64*67]
// ---------------------------------------------------------------------------
extern __shared__ float s_dyn[];

__global__ void __launch_bounds__(256) k_layer(
    const float* __restrict__ W1, const float* __restrict__ b1,
    const float* __restrict__ W2, const float* __restrict__ b2,
    float* __restrict__ out, float scale, int flag) {

    float* sW = s_dyn;                 // 4096 floats
    float* sU = s_dyn + 4096;          // 64 x 67
    float* sV = sU + 64 * 67;          // 64 x 67

    const float* esrc = flag ? g_eb : g_ea;
    float*       edst = flag ? g_ea : g_eb;

    const int tid = threadIdx.x;
    const int tx = tid & 15;
    const int ty = tid >> 4;
    const int base = blockIdx.x * 64;

    // ---- gather phase: 4 slices of (16 nodes x 16 chunks) ----
    #pragma unroll
    for (int it = 0; it < 4; it++) {
        int nd = (tid >> 4) + it * 16;   // local node 0..63
        int c  = tid & 15;               // float4 chunk
        int node = base + nd;
        float4 xa = make_float4(0.f, 0.f, 0.f, 0.f);
        float4 xb = make_float4(0.f, 0.f, 0.f, 0.f);
        float4 ev = make_float4(0.f, 0.f, 0.f, 0.f);
        if (node < N_NODES) {
            int start = g_off[node];
            int deg = g_deg[node];
            int j = 0;
            for (; j + 1 < deg; j += 2) {
                int2 cv0 = g_csr_cv[start + j];
                int2 cv1 = g_csr_cv[start + j + 1];
                float v0 = __int_as_float(cv0.y);
                float v1 = __int_as_float(cv1.y);
                float4 f0 = __ldg(((const float4*)esrc) + cv0.x * 16 + c);
                float4 f1 = __ldg(((const float4*)esrc) + cv1.x * 16 + c);
                xa.x += v0 * f0.x; xa.y += v0 * f0.y; xa.z += v0 * f0.z; xa.w += v0 * f0.w;
                xb.x += v1 * f1.x; xb.y += v1 * f1.y; xb.z += v1 * f1.z; xb.w += v1 * f1.w;
            }
            if (j < deg) {
                int2 cv0 = g_csr_cv[start + j];
                float v0 = __int_as_float(cv0.y);
                float4 f0 = __ldg(((const float4*)esrc) + cv0.x * 16 + c);
                xa.x += v0 * f0.x; xa.y += v0 * f0.y; xa.z += v0 * f0.z; xa.w += v0 * f0.w;
            }
            xa.x += xb.x; xa.y += xb.y; xa.z += xb.z; xa.w += xb.w;
            ev = __ldg(((const float4*)esrc) + node * 16 + c);
        }
        int r0 = c * 4;
        sU[(r0 + 0) * 67 + nd] = ev.x + xa.x;
        sU[(r0 + 1) * 67 + nd] = ev.y + xa.y;
        sU[(r0 + 2) * 67 + nd] = ev.z + xa.z;
        sU[(r0 + 3) * 67 + nd] = ev.w + xa.w;
        sV[(r0 + 0) * 67 + nd] = ev.x * xa.x;
        sV[(r0 + 1) * 67 + nd] = ev.y * xa.y;
        sV[(r0 + 2) * 67 + nd] = ev.z * xa.z;
        sV[(r0 + 3) * 67 + nd] = ev.w * xa.w;
    }

    // ---- GEMM (R3 core): acc[node a][col j] ----
    float acc[4][4];
    #pragma unroll
    for (int a = 0; a < 4; a++)
        #pragma unroll
        for (int j = 0; j < 4; j++) acc[a][j] = 0.f;

    #pragma unroll
    for (int ph = 0; ph < 2; ph++) {
        if (ph) __syncthreads();                  // phase-0 sW reads done
        const float* W = ph ? W2 : W1;
        #pragma unroll
        for (int it = 0; it < 4; it++) {
            int i = tid + it * 256;
            ((float4*)sW)[i] = ((const float4*)W)[i];
        }
        __syncthreads();                          // sW (and, ph0, sU/sV) ready

        const float* S = ph ? sV : sU;
        #pragma unroll 16
        for (int k = 0; k < 64; k++) {
            float4 w = *(const float4*)&sW[k * 64 + tx * 4];
            float u0 = S[k * 67 + ty * 4 + 0];
            float u1 = S[k * 67 + ty * 4 + 1];
            float u2 = S[k * 67 + ty * 4 + 2];
            float u3 = S[k * 67 + ty * 4 + 3];
            acc[0][0] += u0 * w.x; acc[0][1] += u0 * w.y; acc[0][2] += u0 * w.z; acc[0][3] += u0 * w.w;
            acc[1][0] += u1 * w.x; acc[1][1] += u1 * w.y; acc[1][2] += u1 * w.z; acc[1][3] += u1 * w.w;
            acc[2][0] += u2 * w.x; acc[2][1] += u2 * w.y; acc[2][2] += u2 * w.z; acc[2][3] += u2 * w.w;
            acc[3][0] += u3 * w.x; acc[3][1] += u3 * w.y; acc[3][2] += u3 * w.z; acc[3][3] += u3 * w.w;
        }
    }

    // ---- epilogue ----
    const int j0 = tx * 4;
    float bb0 = b1[j0 + 0] + b2[j0 + 0];
    float bb1 = b1[j0 + 1] + b2[j0 + 1];
    float bb2 = b1[j0 + 2] + b2[j0 + 2];
    float bb3 = b1[j0 + 3] + b2[j0 + 3];

    #pragma unroll
    for (int a = 0; a < 4; a++) {
        float h0 = acc[a][0] + bb0;
        float h1 = acc[a][1] + bb1;
        float h2 = acc[a][2] + bb2;
        float h3 = acc[a][3] + bb3;
        h0 = (h0 >= 0.f) ? h0 : NEG_SLOPE * h0;
        h1 = (h1 >= 0.f) ? h1 : NEG_SLOPE * h1;
        h2 = (h2 >= 0.f) ? h2 : NEG_SLOPE * h2;
        h3 = (h3 >= 0.f) ? h3 : NEG_SLOPE * h3;
        float ss = h0 * h0 + h1 * h1 + h2 * h2 + h3 * h3;
        ss += __shfl_xor_sync(0xffffffffu, ss, 1);
        ss += __shfl_xor_sync(0xffffffffu, ss, 2);
        ss += __shfl_xor_sync(0xffffffffu, ss, 4);
        ss += __shfl_xor_sync(0xffffffffu, ss, 8);
        float inv = rsqrtf(fmaxf(ss, 1e-24f));
        float e0 = h0 * inv, e1 = h1 * inv, e2 = h2 * inv, e3 = h3 * inv;

        int node = base + ty * 4 + a;
        if (node < N_NODES) {
            ((float4*)edst)[node * 16 + tx] = make_float4(e0, e1, e2, e3);
            float4 o = ((float4*)out)[node * 16 + tx];
            o.x = (o.x + e0) * scale;
            o.y = (o.y + e1) * scale;
            o.z = (o.z + e2) * scale;
            o.w = (o.w + e3) * scale;
            ((float4*)out)[node * 16 + tx] = o;
        }
    }
}

// ---------------------------------------------------------------------------
extern "C" void kernel_launch(void* const* d_in, const int* in_sizes, int n_in,
                              void* d_out, int out_size) {
    const int*   erow = (const int*)d_in[0];
    const int*   ecol = (const int*)d_in[1];
    const float* eval = (const float*)d_in[2];
    const float* ue   = (const float*)d_in[3];
    const float* ie   = (const float*)d_in[4];
    const float* W1   = (const float*)d_in[5];
    const float* b1   = (const float*)d_in[6];
    const float* W2   = (const float*)d_in[7];
    const float* b2   = (const float*)d_in[8];
    float* out = (float*)d_out;

    const int total4 = N_NODES * EMB / 4;
    const int init_blocks = (total4 + 255) / 256;           // 6250
    const int edge_blocks = (N_EDGES + 255) / 256;          // 5000
    const int node_blocks = (N_NODES + 255) / 256;          // 391
    const int layer_blocks = (N_NODES + 63) / 64;           // 1563
    const int smem_bytes = (4096 + 2 * 64 * 67) * (int)sizeof(float);  // 50688

    cudaFuncSetAttribute(k_layer, cudaFuncAttributeMaxDynamicSharedMemorySize,
                         smem_bytes);

    k_init<<<init_blocks, 256>>>(ue, ie, out);
    k_hist<<<edge_blocks, 256>>>(erow);
    k_scanA<<<NSCAN_BLOCKS, SCAN_BLK>>>();
    k_scanC<<<node_blocks, 256>>>();
    k_scatter<<<edge_blocks, 256>>>(erow, ecol, eval);

    for (int l = 0; l < 3; l++) {
        float scale = (l == 2) ? 0.25f : 1.0f;
        k_layer<<<layer_blocks, 256, smem_bytes>>>(
            W1 + l * EMB * EMB, b1 + l * EMB,
            W2 + l * EMB * EMB, b2 + l * EMB, out, scale, l & 1);
    }
}